// round 1
// baseline (speedup 1.0000x reference)
#include <cuda_runtime.h>
#include <cstdint>
#include <cstddef>

#define BB  2
#define NN  512
#define DD  256
#define DHH 16

// ---------------- scratch (no allocations allowed) ----------------
__device__ float g_Q [BB*NN*DHH];
__device__ float g_K [BB*NN*DHH];
__device__ float g_V [BB*NN*DHH];
__device__ float g_Ni[BB*NN*DHH];
__device__ float g_Nj[BB*NN*DHH];
__device__ float g_Att[BB*NN*NN];          // 2 MB, L2-resident

// ---------------- packed fp32x2 helpers (FFMA2 only via PTX) ----------------
__device__ __forceinline__ unsigned long long ffma2(unsigned long long a,
                                                    unsigned long long b,
                                                    unsigned long long c) {
    unsigned long long d;
    asm("fma.rn.f32x2 %0, %1, %2, %3;" : "=l"(d) : "l"(a), "l"(b), "l"(c));
    return d;
}
__device__ __forceinline__ unsigned long long pack2(float x) {
    unsigned long long r;
    asm("mov.b64 %0, {%1, %2};" : "=l"(r) : "f"(x), "f"(x));
    return r;
}

// ================= K1: node projections Q,K,V,Ni,Nj =================
// grid = B*N blocks, 128 threads. Block handles one x-row; 80 threads compute
// (5 projections x 16 heads), x row staged in shared.
__global__ void proj_kernel(const float* __restrict__ x,
                            const float* __restrict__ Wq,  const float* __restrict__ bq,
                            const float* __restrict__ Wk,  const float* __restrict__ bk,
                            const float* __restrict__ Wv,  const float* __restrict__ bv,
                            const float* __restrict__ Wni, const float* __restrict__ bni,
                            const float* __restrict__ Wnj, const float* __restrict__ bnj) {
    __shared__ float xs[DD];
    const int blk = blockIdx.x;          // b*N + n
    const int t = threadIdx.x;
    xs[t]       = x[blk*DD + t];
    xs[t + 128] = x[blk*DD + t + 128];
    __syncthreads();
    if (t < 80) {
        const int p = t >> 4, h = t & 15;
        const float* W; const float* bias; float* o;
        if      (p == 0) { W = Wq;  bias = bq;  o = g_Q;  }
        else if (p == 1) { W = Wk;  bias = bk;  o = g_K;  }
        else if (p == 2) { W = Wv;  bias = bv;  o = g_V;  }
        else if (p == 3) { W = Wni; bias = bni; o = g_Ni; }
        else             { W = Wnj; bias = bnj; o = g_Nj; }
        float acc = bias[h];
        #pragma unroll 8
        for (int d = 0; d < DD; d++) acc = fmaf(xs[d], W[d*DHH + h], acc);
        o[blk*DHH + h] = acc;
    }
}

// ================= K2: edge projection + e_new + raw Att (fused) =================
// grid = B*N blocks (one per (b,i), 512 rows of e), 256 threads, 2 rows/thread.
// e staged through shared (stride-12 padding: LDS.128 conflict-free), 16 h
// accumulated as 8 packed f32x2 per row. Epilogue fuses +be+Ni+Nj, e_new store,
// and Att = dot(e_new, Q_i*K_j)/4 so e is touched exactly once.
#define CHUNK 8
#define ASTR  12

__global__ __launch_bounds__(256, 3) void edge_kernel(const float* __restrict__ e,
                                                      const float* __restrict__ We,
                                                      const float* __restrict__ be,
                                                      float* __restrict__ outE) {
    __shared__ __align__(16) float We_s[DD*DHH];   // 16 KB
    __shared__ __align__(16) float As[NN*ASTR];    // 24 KB
    __shared__ float Qs[DHH], NiBe[DHH];

    const int tid = threadIdx.x;
    const int blk = blockIdx.x;          // b*N + i
    const int b   = blk >> 9;

    {   // load We (4096 floats)
        const float4* src = (const float4*)We;
        float4* dst = (float4*)We_s;
        #pragma unroll
        for (int k = 0; k < 4; k++) dst[tid + k*256] = src[tid + k*256];
    }
    if (tid < DHH) {
        Qs[tid]   = g_Q [blk*DHH + tid];
        NiBe[tid] = g_Ni[blk*DHH + tid] + be[tid];
    }
    __syncthreads();

    const float* erow = e + (size_t)blk * (NN*DD);

    unsigned long long acc[16];          // [row0 h0..15 | row1 h0..15] as f32x2 pairs
    #pragma unroll
    for (int p = 0; p < 16; p++) acc[p] = 0ull;

    #pragma unroll 1
    for (int s = 0; s < DD/CHUNK; s++) {
        const int dbase = s*CHUNK;
        // ---- stage 512 rows x 8 d (coalesced LDG.128 -> padded shared) ----
        #pragma unroll
        for (int it = 0; it < 4; it++) {
            const int q   = tid + it*256;        // 0..1023
            const int row = q >> 1;
            const int dd  = (q & 1) << 2;
            float4 v = *(const float4*)(erow + (size_t)row*DD + dbase + dd);
            *(float4*)&As[row*ASTR + dd] = v;
        }
        __syncthreads();
        // ---- compute: 8 d, 2 rows, 16 h (8 FFMA2 per row per d) ----
        #pragma unroll
        for (int dd = 0; dd < CHUNK; dd += 4) {
            float a0v[4], a1v[4];
            *(float4*)a0v = *(const float4*)&As[ tid       *ASTR + dd];
            *(float4*)a1v = *(const float4*)&As[(tid + 256)*ASTR + dd];
            #pragma unroll
            for (int k = 0; k < 4; k++) {
                const int d = dbase + dd + k;
                const ulonglong2* wp = (const ulonglong2*)&We_s[d*DHH];
                ulonglong2 w0 = wp[0], w1 = wp[1], w2 = wp[2], w3 = wp[3];
                unsigned long long p0 = pack2(a0v[k]);
                unsigned long long p1 = pack2(a1v[k]);
                acc[0]  = ffma2(p0, w0.x, acc[0]);  acc[1]  = ffma2(p0, w0.y, acc[1]);
                acc[2]  = ffma2(p0, w1.x, acc[2]);  acc[3]  = ffma2(p0, w1.y, acc[3]);
                acc[4]  = ffma2(p0, w2.x, acc[4]);  acc[5]  = ffma2(p0, w2.y, acc[5]);
                acc[6]  = ffma2(p0, w3.x, acc[6]);  acc[7]  = ffma2(p0, w3.y, acc[7]);
                acc[8]  = ffma2(p1, w0.x, acc[8]);  acc[9]  = ffma2(p1, w0.y, acc[9]);
                acc[10] = ffma2(p1, w1.x, acc[10]); acc[11] = ffma2(p1, w1.y, acc[11]);
                acc[12] = ffma2(p1, w2.x, acc[12]); acc[13] = ffma2(p1, w2.y, acc[13]);
                acc[14] = ffma2(p1, w3.x, acc[14]); acc[15] = ffma2(p1, w3.y, acc[15]);
            }
        }
        __syncthreads();
    }

    // ---- epilogue: e_new = E + be + Ni + Nj ; Att = dot(e_new, Q*K)/4 ----
    #pragma unroll
    for (int r = 0; r < 2; r++) {
        const int j = tid + r*256;
        float en[16];
        #pragma unroll
        for (int p = 0; p < 8; p++) {
            float2 f = *(float2*)&acc[r*8 + p];
            en[2*p] = f.x; en[2*p + 1] = f.y;
        }
        const float4* njp = (const float4*)&g_Nj[((size_t)b*NN + j)*DHH];
        const float4* kp  = (const float4*)&g_K [((size_t)b*NN + j)*DHH];
        float4* eo = (float4*)(outE + ((size_t)blk*NN + j)*DHH);
        float att = 0.f;
        #pragma unroll
        for (int q4 = 0; q4 < 4; q4++) {
            float4 nj = njp[q4], kk = kp[q4];
            float4 ev;
            ev.x = en[4*q4+0] + NiBe[4*q4+0] + nj.x;
            ev.y = en[4*q4+1] + NiBe[4*q4+1] + nj.y;
            ev.z = en[4*q4+2] + NiBe[4*q4+2] + nj.z;
            ev.w = en[4*q4+3] + NiBe[4*q4+3] + nj.w;
            att = fmaf(ev.x, Qs[4*q4+0]*kk.x, att);
            att = fmaf(ev.y, Qs[4*q4+1]*kk.y, att);
            att = fmaf(ev.z, Qs[4*q4+2]*kk.z, att);
            att = fmaf(ev.w, Qs[4*q4+3]*kk.w, att);
            eo[q4] = ev;
        }
        g_Att[(size_t)blk*NN + j] = att * 0.25f;   // / sqrt(DH=16)
    }
}

// ================= K3: softmax over axis i (per (b,j) column), in place =================
__global__ void softmax_kernel() {
    __shared__ float red[8];
    __shared__ float sval;
    const int blk = blockIdx.x;              // b*N + j
    const int b = blk >> 9, j = blk & 511;
    const int t = threadIdx.x;               // 256
    float* base = g_Att + (size_t)b*NN*NN + j;
    float v0 = base[(size_t)t*NN];
    float v1 = base[(size_t)(t + 256)*NN];

    float m = fmaxf(v0, v1);
    #pragma unroll
    for (int o = 16; o > 0; o >>= 1) m = fmaxf(m, __shfl_xor_sync(0xffffffffu, m, o));
    if ((t & 31) == 0) red[t >> 5] = m;
    __syncthreads();
    if (t == 0) {
        float mm = red[0];
        #pragma unroll
        for (int k = 1; k < 8; k++) mm = fmaxf(mm, red[k]);
        sval = mm;
    }
    __syncthreads();
    const float mx = sval;
    float e0 = __expf(v0 - mx), e1 = __expf(v1 - mx);
    float s = e0 + e1;
    #pragma unroll
    for (int o = 16; o > 0; o >>= 1) s += __shfl_xor_sync(0xffffffffu, s, o);
    if ((t & 31) == 0) red[t >> 5] = s;
    __syncthreads();
    if (t == 0) {
        float ss = 0.f;
        #pragma unroll
        for (int k = 0; k < 8; k++) ss += red[k];
        sval = ss;
    }
    __syncthreads();
    const float inv = 1.0f / sval;
    base[(size_t)t*NN]         = e0 * inv;
    base[(size_t)(t + 256)*NN] = e1 * inv;
}

// ================= K4: out = Att @ V =================
__global__ void out_kernel(float* __restrict__ out) {
    const int g = blockIdx.x*256 + threadIdx.x;    // 0..16383
    const int h = g & 15, i = (g >> 4) & 511, b = g >> 13;
    const float* arow = g_Att + (size_t)b*NN*NN + (size_t)i*NN;
    const float* vb   = g_V   + (size_t)b*NN*DHH + h;
    float acc = 0.f;
    #pragma unroll 8
    for (int j = 0; j < NN; j++) acc = fmaf(arow[j], vb[j*DHH], acc);
    out[g] = acc;
}

// ================= launch =================
extern "C" void kernel_launch(void* const* d_in, const int* in_sizes, int n_in,
                              void* d_out, int out_size) {
    const float* x   = (const float*)d_in[0];
    const float* e   = (const float*)d_in[1];
    const float* Wq  = (const float*)d_in[2];
    const float* bq  = (const float*)d_in[3];
    const float* Wk  = (const float*)d_in[4];
    const float* bk  = (const float*)d_in[5];
    const float* We  = (const float*)d_in[6];
    const float* be  = (const float*)d_in[7];
    const float* Wv  = (const float*)d_in[8];
    const float* bv  = (const float*)d_in[9];
    const float* Wni = (const float*)d_in[10];
    const float* bni = (const float*)d_in[11];
    const float* Wnj = (const float*)d_in[12];
    const float* bnj = (const float*)d_in[13];

    float* out  = (float*)d_out;              // [B,N,DH] first
    float* outE = out + BB*NN*DHH;            // then e_new [B,N,N,DH]

    proj_kernel   <<<BB*NN, 128>>>(x, Wq, bq, Wk, bk, Wv, bv, Wni, bni, Wnj, bnj);
    edge_kernel   <<<BB*NN, 256>>>(e, We, be, outE);
    softmax_kernel<<<BB*NN, 256>>>();
    out_kernel    <<<(BB*NN*DHH)/256, 256>>>(out);
}

// round 2
// speedup vs baseline: 1.3237x; 1.3237x over previous
#include <cuda_runtime.h>
#include <cstdint>
#include <cstddef>

#define BB  2
#define NN  512
#define DD  256
#define DHH 16

// ---------------- scratch (no allocations allowed) ----------------
__device__ float g_Q [BB*NN*DHH];
__device__ float g_K [BB*NN*DHH];
__device__ float g_V [BB*NN*DHH];
__device__ float g_Ni[BB*NN*DHH];
__device__ float g_Nj[BB*NN*DHH];
__device__ float g_Att[BB*NN*NN];          // 2 MB, L2-resident

// ---------------- packed fp32x2 helpers (FFMA2 only via PTX) ----------------
__device__ __forceinline__ unsigned long long ffma2(unsigned long long a,
                                                    unsigned long long b,
                                                    unsigned long long c) {
    unsigned long long d;
    asm("fma.rn.f32x2 %0, %1, %2, %3;" : "=l"(d) : "l"(a), "l"(b), "l"(c));
    return d;
}
__device__ __forceinline__ unsigned long long pack2(float x) {
    unsigned long long r;
    asm("mov.b64 %0, {%1, %2};" : "=l"(r) : "f"(x), "f"(x));
    return r;
}

// ================= K1: node projections Q,K,V,Ni,Nj =================
__global__ void proj_kernel(const float* __restrict__ x,
                            const float* __restrict__ Wq,  const float* __restrict__ bq,
                            const float* __restrict__ Wk,  const float* __restrict__ bk,
                            const float* __restrict__ Wv,  const float* __restrict__ bv,
                            const float* __restrict__ Wni, const float* __restrict__ bni,
                            const float* __restrict__ Wnj, const float* __restrict__ bnj) {
    __shared__ float xs[DD];
    const int blk = blockIdx.x;          // b*N + n
    const int t = threadIdx.x;
    xs[t]       = x[blk*DD + t];
    xs[t + 128] = x[blk*DD + t + 128];
    __syncthreads();
    if (t < 80) {
        const int p = t >> 4, h = t & 15;
        const float* W; const float* bias; float* o;
        if      (p == 0) { W = Wq;  bias = bq;  o = g_Q;  }
        else if (p == 1) { W = Wk;  bias = bk;  o = g_K;  }
        else if (p == 2) { W = Wv;  bias = bv;  o = g_V;  }
        else if (p == 3) { W = Wni; bias = bni; o = g_Ni; }
        else             { W = Wnj; bias = bnj; o = g_Nj; }
        float acc = bias[h];
        #pragma unroll 8
        for (int d = 0; d < DD; d++) acc = fmaf(xs[d], W[d*DHH + h], acc);
        o[blk*DHH + h] = acc;
    }
}

// ================= K2: edge projection + e_new + raw Att (fused) =================
// One block per (b,i). 128 threads, 4 rows/thread. d chunked by 32 floats
// (= 128B = one cache line per row) so staging LDG/STS are line-coalesced.
// As padded to stride 36 floats: conflict-free for .128 ops AND 16B-aligned.
// We broadcast-loads amortized over 4 rows. 2 CTAs/SM alternate stage/compute.
#define ECHUNK 32
#define ASTR   36
#define E_SMEM_BYTES ((DD*DHH + NN*ASTR + 32) * 4)

__global__ __launch_bounds__(128, 2) void edge_kernel(const float* __restrict__ e,
                                                      const float* __restrict__ We,
                                                      const float* __restrict__ be,
                                                      float* __restrict__ outE) {
    extern __shared__ float sm[];
    float* We_s = sm;                    // 4096 floats (16 KB)
    float* As   = sm + DD*DHH;           // 512*36 floats (72 KB)
    float* Qs   = As + NN*ASTR;          // 16
    float* NiBe = Qs + 16;               // 16

    const int tid = threadIdx.x;
    const int blk = blockIdx.x;          // b*N + i
    const int b   = blk >> 9;

    {   // load We (4096 floats, 32 per thread)
        const float4* src = (const float4*)We;
        float4* dst = (float4*)We_s;
        #pragma unroll
        for (int k = 0; k < 8; k++) dst[tid + k*128] = src[tid + k*128];
    }
    if (tid < DHH) {
        Qs[tid]   = g_Q [blk*DHH + tid];
        NiBe[tid] = g_Ni[blk*DHH + tid] + be[tid];
    }
    __syncthreads();

    const float* erow = e + (size_t)blk * (NN*DD);

    unsigned long long acc[4][8];        // 4 rows x 16 h (f32x2 pairs)
    #pragma unroll
    for (int r = 0; r < 4; r++)
        #pragma unroll
        for (int p = 0; p < 8; p++) acc[r][p] = 0ull;

    #pragma unroll 1
    for (int c = 0; c < DD/ECHUNK; c++) {
        const int dbase = c * ECHUNK;
        // ---- stage 512 rows x 128B, line-coalesced (8 lanes cover one row-line) ----
        #pragma unroll 8
        for (int it = 0; it < 32; it++) {
            const int q   = it*128 + tid;       // 0..4095
            const int row = q >> 3;
            const int dc  = (q & 7) << 2;
            float4 v = *(const float4*)(erow + (size_t)row*DD + dbase + dc);
            *(float4*)&As[row*ASTR + dc] = v;
        }
        __syncthreads();
        // ---- compute: 32 d x 4 rows x 16 h ----
        #pragma unroll
        for (int dd = 0; dd < ECHUNK; dd += 4) {
            float a0[4], a1[4], a2[4], a3[4];
            *(float4*)a0 = *(const float4*)&As[(tid      )*ASTR + dd];
            *(float4*)a1 = *(const float4*)&As[(tid + 128)*ASTR + dd];
            *(float4*)a2 = *(const float4*)&As[(tid + 256)*ASTR + dd];
            *(float4*)a3 = *(const float4*)&As[(tid + 384)*ASTR + dd];
            #pragma unroll
            for (int k = 0; k < 4; k++) {
                const ulonglong2* wp = (const ulonglong2*)&We_s[(dbase + dd + k)*DHH];
                ulonglong2 wA = wp[0], wB = wp[1], wC = wp[2], wD = wp[3];
                unsigned long long p0 = pack2(a0[k]);
                unsigned long long p1 = pack2(a1[k]);
                unsigned long long p2 = pack2(a2[k]);
                unsigned long long p3 = pack2(a3[k]);
                acc[0][0]=ffma2(p0,wA.x,acc[0][0]); acc[0][1]=ffma2(p0,wA.y,acc[0][1]);
                acc[0][2]=ffma2(p0,wB.x,acc[0][2]); acc[0][3]=ffma2(p0,wB.y,acc[0][3]);
                acc[0][4]=ffma2(p0,wC.x,acc[0][4]); acc[0][5]=ffma2(p0,wC.y,acc[0][5]);
                acc[0][6]=ffma2(p0,wD.x,acc[0][6]); acc[0][7]=ffma2(p0,wD.y,acc[0][7]);
                acc[1][0]=ffma2(p1,wA.x,acc[1][0]); acc[1][1]=ffma2(p1,wA.y,acc[1][1]);
                acc[1][2]=ffma2(p1,wB.x,acc[1][2]); acc[1][3]=ffma2(p1,wB.y,acc[1][3]);
                acc[1][4]=ffma2(p1,wC.x,acc[1][4]); acc[1][5]=ffma2(p1,wC.y,acc[1][5]);
                acc[1][6]=ffma2(p1,wD.x,acc[1][6]); acc[1][7]=ffma2(p1,wD.y,acc[1][7]);
                acc[2][0]=ffma2(p2,wA.x,acc[2][0]); acc[2][1]=ffma2(p2,wA.y,acc[2][1]);
                acc[2][2]=ffma2(p2,wB.x,acc[2][2]); acc[2][3]=ffma2(p2,wB.y,acc[2][3]);
                acc[2][4]=ffma2(p2,wC.x,acc[2][4]); acc[2][5]=ffma2(p2,wC.y,acc[2][5]);
                acc[2][6]=ffma2(p2,wD.x,acc[2][6]); acc[2][7]=ffma2(p2,wD.y,acc[2][7]);
                acc[3][0]=ffma2(p3,wA.x,acc[3][0]); acc[3][1]=ffma2(p3,wA.y,acc[3][1]);
                acc[3][2]=ffma2(p3,wB.x,acc[3][2]); acc[3][3]=ffma2(p3,wB.y,acc[3][3]);
                acc[3][4]=ffma2(p3,wC.x,acc[3][4]); acc[3][5]=ffma2(p3,wC.y,acc[3][5]);
                acc[3][6]=ffma2(p3,wD.x,acc[3][6]); acc[3][7]=ffma2(p3,wD.y,acc[3][7]);
            }
        }
        __syncthreads();
    }

    // ---- epilogue: e_new = E + be + Ni + Nj ; Att = dot(e_new, Q*K)/4 ----
    #pragma unroll
    for (int r = 0; r < 4; r++) {
        const int j = tid + r*128;
        float en[16];
        #pragma unroll
        for (int p = 0; p < 8; p++) {
            float2 f = *(float2*)&acc[r][p];
            en[2*p] = f.x; en[2*p + 1] = f.y;
        }
        const float4* njp = (const float4*)&g_Nj[((size_t)b*NN + j)*DHH];
        const float4* kp  = (const float4*)&g_K [((size_t)b*NN + j)*DHH];
        float4* eo = (float4*)(outE + ((size_t)blk*NN + j)*DHH);
        float att = 0.f;
        #pragma unroll
        for (int q4 = 0; q4 < 4; q4++) {
            float4 nj = njp[q4], kk = kp[q4];
            float4 ev;
            ev.x = en[4*q4+0] + NiBe[4*q4+0] + nj.x;
            ev.y = en[4*q4+1] + NiBe[4*q4+1] + nj.y;
            ev.z = en[4*q4+2] + NiBe[4*q4+2] + nj.z;
            ev.w = en[4*q4+3] + NiBe[4*q4+3] + nj.w;
            att = fmaf(ev.x, Qs[4*q4+0]*kk.x, att);
            att = fmaf(ev.y, Qs[4*q4+1]*kk.y, att);
            att = fmaf(ev.z, Qs[4*q4+2]*kk.z, att);
            att = fmaf(ev.w, Qs[4*q4+3]*kk.w, att);
            eo[q4] = ev;
        }
        g_Att[(size_t)blk*NN + j] = att * 0.25f;   // / sqrt(DH=16)
    }
}

// ================= K3: softmax over axis i (per (b,j) column), in place =================
__global__ void softmax_kernel() {
    __shared__ float red[8];
    __shared__ float sval;
    const int blk = blockIdx.x;              // b*N + j
    const int b = blk >> 9, j = blk & 511;
    const int t = threadIdx.x;               // 256
    float* base = g_Att + (size_t)b*NN*NN + j;
    float v0 = base[(size_t)t*NN];
    float v1 = base[(size_t)(t + 256)*NN];

    float m = fmaxf(v0, v1);
    #pragma unroll
    for (int o = 16; o > 0; o >>= 1) m = fmaxf(m, __shfl_xor_sync(0xffffffffu, m, o));
    if ((t & 31) == 0) red[t >> 5] = m;
    __syncthreads();
    if (t == 0) {
        float mm = red[0];
        #pragma unroll
        for (int k = 1; k < 8; k++) mm = fmaxf(mm, red[k]);
        sval = mm;
    }
    __syncthreads();
    const float mx = sval;
    float e0 = __expf(v0 - mx), e1 = __expf(v1 - mx);
    float s = e0 + e1;
    #pragma unroll
    for (int o = 16; o > 0; o >>= 1) s += __shfl_xor_sync(0xffffffffu, s, o);
    if ((t & 31) == 0) red[t >> 5] = s;
    __syncthreads();
    if (t == 0) {
        float ss = 0.f;
        #pragma unroll
        for (int k = 0; k < 8; k++) ss += red[k];
        sval = ss;
    }
    __syncthreads();
    const float inv = 1.0f / sval;
    base[(size_t)t*NN]         = e0 * inv;
    base[(size_t)(t + 256)*NN] = e1 * inv;
}

// ================= K4: out = Att @ V (block per (b,i), tree reduction) =================
__global__ void out_kernel(float* __restrict__ out) {
    __shared__ float red[128][20];           // pad 20: 16B-aligned rows, conflict-free
    const int blk = blockIdx.x;              // b*N + i
    const int b = blk >> 9;
    const int t = threadIdx.x;               // 128
    const float* arow = g_Att + (size_t)blk*NN;
    float acc[16];
    #pragma unroll
    for (int h = 0; h < 16; h++) acc[h] = 0.f;
    #pragma unroll
    for (int r = 0; r < 4; r++) {
        const int j = t + r*128;
        const float a = arow[j];
        const float4* v = (const float4*)&g_V[((size_t)b*NN + j)*DHH];
        float4 v0 = v[0], v1 = v[1], v2 = v[2], v3 = v[3];
        acc[0]  = fmaf(a, v0.x, acc[0]);  acc[1]  = fmaf(a, v0.y, acc[1]);
        acc[2]  = fmaf(a, v0.z, acc[2]);  acc[3]  = fmaf(a, v0.w, acc[3]);
        acc[4]  = fmaf(a, v1.x, acc[4]);  acc[5]  = fmaf(a, v1.y, acc[5]);
        acc[6]  = fmaf(a, v1.z, acc[6]);  acc[7]  = fmaf(a, v1.w, acc[7]);
        acc[8]  = fmaf(a, v2.x, acc[8]);  acc[9]  = fmaf(a, v2.y, acc[9]);
        acc[10] = fmaf(a, v2.z, acc[10]); acc[11] = fmaf(a, v2.w, acc[11]);
        acc[12] = fmaf(a, v3.x, acc[12]); acc[13] = fmaf(a, v3.y, acc[13]);
        acc[14] = fmaf(a, v3.z, acc[14]); acc[15] = fmaf(a, v3.w, acc[15]);
    }
    #pragma unroll
    for (int q4 = 0; q4 < 4; q4++)
        *(float4*)&red[t][q4*4] = *(float4*)&acc[q4*4];
    __syncthreads();
    #pragma unroll
    for (int s = 64; s > 0; s >>= 1) {
        if (t < s) {
            #pragma unroll
            for (int q4 = 0; q4 < 4; q4++) {
                float4 x = *(float4*)&red[t][q4*4];
                float4 y = *(float4*)&red[t + s][q4*4];
                x.x += y.x; x.y += y.y; x.z += y.z; x.w += y.w;
                *(float4*)&red[t][q4*4] = x;
            }
        }
        __syncthreads();
    }
    if (t < DHH) out[blk*DHH + t] = red[0][t];
}

// ================= launch =================
extern "C" void kernel_launch(void* const* d_in, const int* in_sizes, int n_in,
                              void* d_out, int out_size) {
    const float* x   = (const float*)d_in[0];
    const float* e   = (const float*)d_in[1];
    const float* Wq  = (const float*)d_in[2];
    const float* bq  = (const float*)d_in[3];
    const float* Wk  = (const float*)d_in[4];
    const float* bk  = (const float*)d_in[5];
    const float* We  = (const float*)d_in[6];
    const float* be  = (const float*)d_in[7];
    const float* Wv  = (const float*)d_in[8];
    const float* bv  = (const float*)d_in[9];
    const float* Wni = (const float*)d_in[10];
    const float* bni = (const float*)d_in[11];
    const float* Wnj = (const float*)d_in[12];
    const float* bnj = (const float*)d_in[13];

    float* out  = (float*)d_out;              // [B,N,DH] first
    float* outE = out + BB*NN*DHH;            // then e_new [B,N,N,DH]

    cudaFuncSetAttribute(edge_kernel, cudaFuncAttributeMaxDynamicSharedMemorySize,
                         E_SMEM_BYTES);

    proj_kernel   <<<BB*NN, 128>>>(x, Wq, bq, Wk, bk, Wv, bv, Wni, bni, Wnj, bnj);
    edge_kernel   <<<BB*NN, 128, E_SMEM_BYTES>>>(e, We, be, outE);
    softmax_kernel<<<BB*NN, 256>>>();
    out_kernel    <<<BB*NN, 128>>>(out);
}

// round 7
// speedup vs baseline: 1.5121x; 1.1423x over previous
#include <cuda_runtime.h>
#include <cstdint>
#include <cstddef>

#define BB  2
#define NN  512
#define DD  256
#define DHH 16

// ---------------- scratch (no allocations allowed) ----------------
__device__ float g_Q [BB*NN*DHH];
__device__ float g_K [BB*NN*DHH];
__device__ float g_V [BB*NN*DHH];
__device__ float g_Ni[BB*NN*DHH];
__device__ float g_Nj[BB*NN*DHH];
__device__ float g_Att[BB*NN*NN];          // 2 MB, L2-resident

// ---------------- packed fp32x2 helpers (FFMA2 only via PTX) ----------------
__device__ __forceinline__ unsigned long long ffma2(unsigned long long a,
                                                    unsigned long long b,
                                                    unsigned long long c) {
    unsigned long long d;
    asm("fma.rn.f32x2 %0, %1, %2, %3;" : "=l"(d) : "l"(a), "l"(b), "l"(c));
    return d;
}
__device__ __forceinline__ unsigned long long pack2(float x) {
    unsigned long long r;
    asm("mov.b64 %0, {%1, %2};" : "=l"(r) : "f"(x), "f"(x));
    return r;
}

// ================= K1: node projections Q,K,V,Ni,Nj =================
__global__ void proj_kernel(const float* __restrict__ x,
                            const float* __restrict__ Wq,  const float* __restrict__ bq,
                            const float* __restrict__ Wk,  const float* __restrict__ bk,
                            const float* __restrict__ Wv,  const float* __restrict__ bv,
                            const float* __restrict__ Wni, const float* __restrict__ bni,
                            const float* __restrict__ Wnj, const float* __restrict__ bnj) {
    __shared__ float xs[DD];
    const int blk = blockIdx.x;          // b*N + n
    const int t = threadIdx.x;
    xs[t]       = x[blk*DD + t];
    xs[t + 128] = x[blk*DD + t + 128];
    __syncthreads();
    if (t < 80) {
        const int p = t >> 4, h = t & 15;
        const float* W; const float* bias; float* o;
        if      (p == 0) { W = Wq;  bias = bq;  o = g_Q;  }
        else if (p == 1) { W = Wk;  bias = bk;  o = g_K;  }
        else if (p == 2) { W = Wv;  bias = bv;  o = g_V;  }
        else if (p == 3) { W = Wni; bias = bni; o = g_Ni; }
        else             { W = Wnj; bias = bnj; o = g_Nj; }
        float acc = bias[h];
        #pragma unroll 8
        for (int d = 0; d < DD; d++) acc = fmaf(xs[d], W[d*DHH + h], acc);
        o[blk*DHH + h] = acc;
    }
}

// ================= K2: edge projection + e_new + raw Att (register-prefetch pipeline) =================
// One block per (b,i). 256 threads, 2 rows/thread, 512 rows. d chunked by 32
// floats (128B line/row). Pipeline: while chunk c computes from shared, the 16
// LDG.128 for chunk c+1 are in flight into registers (latency hidden by the
// ~2048-cycle compute phase); STS happens after the compute barrier.
// Single As buffer (72KB) + We (16KB) = 88KB smem. No cp.async.
#define ECHUNK 32
#define ASTR   36
#define E_SMEM_BYTES ((DD*DHH + NN*ASTR + 32) * 4)

__global__ __launch_bounds__(256) void edge_kernel(const float* __restrict__ e,
                                                   const float* __restrict__ We,
                                                   const float* __restrict__ be,
                                                   float* __restrict__ outE) {
    extern __shared__ float sm[];
    float* We_s = sm;                    // 4096 floats (16 KB)
    float* As   = sm + DD*DHH;           // 512*36 floats (72 KB)
    float* Qs   = As + NN*ASTR;          // 16
    float* NiBe = Qs + 16;               // 16

    const int tid = threadIdx.x;
    const int blk = blockIdx.x;          // b*N + i
    const int b   = blk >> 9;

    {   // load We (4096 floats, 16 per thread)
        const float4* src = (const float4*)We;
        float4* dst = (float4*)We_s;
        #pragma unroll
        for (int k = 0; k < 4; k++) dst[tid + k*256] = src[tid + k*256];
    }
    if (tid < DHH) {
        Qs[tid]   = g_Q [blk*DHH + tid];
        NiBe[tid] = g_Ni[blk*DHH + tid] + be[tid];
    }

    const float* erow = e + (size_t)blk * (NN*DD);

    // per-thread staging geometry: 16 float4 per chunk (8 lanes cover one 128B row-line)
    const int srow = tid >> 3;           // base row, advances by 32 per it
    const int sdc  = (tid & 7) << 2;     // float offset within the 32-float chunk

    float4 pref[16];
    // ---- prologue: fetch chunk 0 into registers, stage to shared ----
    #pragma unroll
    for (int it = 0; it < 16; it++)
        pref[it] = *(const float4*)(erow + (size_t)(srow + it*32)*DD + sdc);
    #pragma unroll
    for (int it = 0; it < 16; it++)
        *(float4*)&As[(srow + it*32)*ASTR + sdc] = pref[it];
    __syncthreads();

    unsigned long long acc[2][8];        // 2 rows x 16 h (f32x2 pairs)
    #pragma unroll
    for (int r = 0; r < 2; r++)
        #pragma unroll
        for (int p = 0; p < 8; p++) acc[r][p] = 0ull;

    #pragma unroll 1
    for (int c = 0; c < DD/ECHUNK; c++) {
        // ---- issue prefetch LDGs for chunk c+1 (in flight during compute) ----
        if (c < DD/ECHUNK - 1) {
            const int dbn = (c + 1) * ECHUNK;
            #pragma unroll
            for (int it = 0; it < 16; it++)
                pref[it] = *(const float4*)(erow + (size_t)(srow + it*32)*DD + dbn + sdc);
        }
        // ---- compute chunk c: 32 d x 2 rows x 16 h ----
        const int dbase = c * ECHUNK;
        #pragma unroll
        for (int dd = 0; dd < ECHUNK; dd += 4) {
            float a0[4], a1[4];
            *(float4*)a0 = *(const float4*)&As[(tid      )*ASTR + dd];
            *(float4*)a1 = *(const float4*)&As[(tid + 256)*ASTR + dd];
            #pragma unroll
            for (int k = 0; k < 4; k++) {
                const ulonglong2* wp = (const ulonglong2*)&We_s[(dbase + dd + k)*DHH];
                ulonglong2 wA = wp[0], wB = wp[1], wC = wp[2], wD = wp[3];
                unsigned long long p0 = pack2(a0[k]);
                unsigned long long p1 = pack2(a1[k]);
                acc[0][0]=ffma2(p0,wA.x,acc[0][0]); acc[0][1]=ffma2(p0,wA.y,acc[0][1]);
                acc[0][2]=ffma2(p0,wB.x,acc[0][2]); acc[0][3]=ffma2(p0,wB.y,acc[0][3]);
                acc[0][4]=ffma2(p0,wC.x,acc[0][4]); acc[0][5]=ffma2(p0,wC.y,acc[0][5]);
                acc[0][6]=ffma2(p0,wD.x,acc[0][6]); acc[0][7]=ffma2(p0,wD.y,acc[0][7]);
                acc[1][0]=ffma2(p1,wA.x,acc[1][0]); acc[1][1]=ffma2(p1,wA.y,acc[1][1]);
                acc[1][2]=ffma2(p1,wB.x,acc[1][2]); acc[1][3]=ffma2(p1,wB.y,acc[1][3]);
                acc[1][4]=ffma2(p1,wC.x,acc[1][4]); acc[1][5]=ffma2(p1,wC.y,acc[1][5]);
                acc[1][6]=ffma2(p1,wD.x,acc[1][6]); acc[1][7]=ffma2(p1,wD.y,acc[1][7]);
            }
        }
        __syncthreads();                 // all readers done with As
        if (c < DD/ECHUNK - 1) {
            #pragma unroll
            for (int it = 0; it < 16; it++)
                *(float4*)&As[(srow + it*32)*ASTR + sdc] = pref[it];
        }
        __syncthreads();                 // As holds chunk c+1
    }

    // ---- epilogue: e_new = E + be + Ni + Nj ; Att = dot(e_new, Q*K)/4 ----
    float attv[2];
    #pragma unroll
    for (int r = 0; r < 2; r++) {
        const int j = tid + r*256;
        float en[16];
        #pragma unroll
        for (int p = 0; p < 8; p++) {
            float2 f = *(float2*)&acc[r][p];
            en[2*p] = f.x; en[2*p + 1] = f.y;
        }
        const float4* njp = (const float4*)&g_Nj[((size_t)b*NN + j)*DHH];
        const float4* kp  = (const float4*)&g_K [((size_t)b*NN + j)*DHH];
        float4* eo = (float4*)(outE + ((size_t)blk*NN + j)*DHH);
        float att = 0.f;
        #pragma unroll
        for (int q4 = 0; q4 < 4; q4++) {
            float4 nj = njp[q4], kk = kp[q4];
            float4 ev;
            ev.x = en[4*q4+0] + NiBe[4*q4+0] + nj.x;
            ev.y = en[4*q4+1] + NiBe[4*q4+1] + nj.y;
            ev.z = en[4*q4+2] + NiBe[4*q4+2] + nj.z;
            ev.w = en[4*q4+3] + NiBe[4*q4+3] + nj.w;
            att = fmaf(ev.x, Qs[4*q4+0]*kk.x, att);
            att = fmaf(ev.y, Qs[4*q4+1]*kk.y, att);
            att = fmaf(ev.z, Qs[4*q4+2]*kk.z, att);
            att = fmaf(ev.w, Qs[4*q4+3]*kk.w, att);
            eo[q4] = ev;
        }
        attv[r] = att * 0.25f;               // / sqrt(DH=16)
    }
    g_Att[(size_t)blk*NN + tid]       = attv[0];
    g_Att[(size_t)blk*NN + tid + 256] = attv[1];
}

// ================= K3: softmax over axis i (per (b,j) column), in place =================
__global__ void softmax_kernel() {
    __shared__ float red[8];
    __shared__ float sval;
    const int blk = blockIdx.x;              // b*N + j
    const int b = blk >> 9, j = blk & 511;
    const int t = threadIdx.x;               // 256
    float* base = g_Att + (size_t)b*NN*NN + j;
    float v0 = base[(size_t)t*NN];
    float v1 = base[(size_t)(t + 256)*NN];

    float m = fmaxf(v0, v1);
    #pragma unroll
    for (int o = 16; o > 0; o >>= 1) m = fmaxf(m, __shfl_xor_sync(0xffffffffu, m, o));
    if ((t & 31) == 0) red[t >> 5] = m;
    __syncthreads();
    if (t == 0) {
        float mm = red[0];
        #pragma unroll
        for (int k = 1; k < 8; k++) mm = fmaxf(mm, red[k]);
        sval = mm;
    }
    __syncthreads();
    const float mx = sval;
    float e0 = __expf(v0 - mx), e1 = __expf(v1 - mx);
    float s = e0 + e1;
    #pragma unroll
    for (int o = 16; o > 0; o >>= 1) s += __shfl_xor_sync(0xffffffffu, s, o);
    if ((t & 31) == 0) red[t >> 5] = s;
    __syncthreads();
    if (t == 0) {
        float ss = 0.f;
        #pragma unroll
        for (int k = 0; k < 8; k++) ss += red[k];
        sval = ss;
    }
    __syncthreads();
    const float inv = 1.0f / sval;
    base[(size_t)t*NN]         = e0 * inv;
    base[(size_t)(t + 256)*NN] = e1 * inv;
}

// ================= K4: out = Att @ V (block per (b,i), tree reduction) =================
__global__ void out_kernel(float* __restrict__ out) {
    __shared__ float red[128][20];           // pad 20: 16B-aligned rows, conflict-free
    const int blk = blockIdx.x;              // b*N + i
    const int b = blk >> 9;
    const int t = threadIdx.x;               // 128
    const float* arow = g_Att + (size_t)blk*NN;
    float acc[16];
    #pragma unroll
    for (int h = 0; h < 16; h++) acc[h] = 0.f;
    #pragma unroll
    for (int r = 0; r < 4; r++) {
        const int j = t + r*128;
        const float a = arow[j];
        const float4* v = (const float4*)&g_V[((size_t)b*NN + j)*DHH];
        float4 v0 = v[0], v1 = v[1], v2 = v[2], v3 = v[3];
        acc[0]  = fmaf(a, v0.x, acc[0]);  acc[1]  = fmaf(a, v0.y, acc[1]);
        acc[2]  = fmaf(a, v0.z, acc[2]);  acc[3]  = fmaf(a, v0.w, acc[3]);
        acc[4]  = fmaf(a, v1.x, acc[4]);  acc[5]  = fmaf(a, v1.y, acc[5]);
        acc[6]  = fmaf(a, v1.z, acc[6]);  acc[7]  = fmaf(a, v1.w, acc[7]);
        acc[8]  = fmaf(a, v2.x, acc[8]);  acc[9]  = fmaf(a, v2.y, acc[9]);
        acc[10] = fmaf(a, v2.z, acc[10]); acc[11] = fmaf(a, v2.w, acc[11]);
        acc[12] = fmaf(a, v3.x, acc[12]); acc[13] = fmaf(a, v3.y, acc[13]);
        acc[14] = fmaf(a, v3.z, acc[14]); acc[15] = fmaf(a, v3.w, acc[15]);
    }
    #pragma unroll
    for (int q4 = 0; q4 < 4; q4++)
        *(float4*)&red[t][q4*4] = *(float4*)&acc[q4*4];
    __syncthreads();
    #pragma unroll
    for (int s = 64; s > 0; s >>= 1) {
        if (t < s) {
            #pragma unroll
            for (int q4 = 0; q4 < 4; q4++) {
                float4 x = *(float4*)&red[t][q4*4];
                float4 y = *(float4*)&red[t + s][q4*4];
                x.x += y.x; x.y += y.y; x.z += y.z; x.w += y.w;
                *(float4*)&red[t][q4*4] = x;
            }
        }
        __syncthreads();
    }
    if (t < DHH) out[blk*DHH + t] = red[0][t];
}

// ================= launch =================
extern "C" void kernel_launch(void* const* d_in, const int* in_sizes, int n_in,
                              void* d_out, int out_size) {
    const float* x   = (const float*)d_in[0];
    const float* e   = (const float*)d_in[1];
    const float* Wq  = (const float*)d_in[2];
    const float* bq  = (const float*)d_in[3];
    const float* Wk  = (const float*)d_in[4];
    const float* bk  = (const float*)d_in[5];
    const float* We  = (const float*)d_in[6];
    const float* be  = (const float*)d_in[7];
    const float* Wv  = (const float*)d_in[8];
    const float* bv  = (const float*)d_in[9];
    const float* Wni = (const float*)d_in[10];
    const float* bni = (const float*)d_in[11];
    const float* Wnj = (const float*)d_in[12];
    const float* bnj = (const float*)d_in[13];

    float* out  = (float*)d_out;              // [B,N,DH] first
    float* outE = out + BB*NN*DHH;            // then e_new [B,N,N,DH]

    cudaFuncSetAttribute(edge_kernel, cudaFuncAttributeMaxDynamicSharedMemorySize,
                         E_SMEM_BYTES);

    proj_kernel   <<<BB*NN, 128>>>(x, Wq, bq, Wk, bk, Wv, bv, Wni, bni, Wnj, bnj);
    edge_kernel   <<<BB*NN, 256, E_SMEM_BYTES>>>(e, We, be, outE);
    softmax_kernel<<<BB*NN, 256>>>();
    out_kernel    <<<BB*NN, 128>>>(out);
}